// round 15
// baseline (speedup 1.0000x reference)
#include <cuda_runtime.h>
#include <cuda_fp16.h>
#include <stdint.h>

#define N_NODES 100000
#define N_EDGES 3200000
#define F 128
#define T_POINTS 4

#define SCAN_CHUNK 512
#define SCAN_NBLK ((N_NODES + SCAN_CHUNK - 1) / SCAN_CHUNK)   // 196

// ---- scratch (device globals; no allocations allowed) ----
__device__ __half g_support[(size_t)N_NODES * F];  // GEMM out / SPMM gather src
__device__ __half g_hh[(size_t)N_NODES * F];       // layer output fp16 -> next GEMM A
__device__ __half g_W1h[256 * 128];
__device__ __half g_W2h[128 * 128];
__device__ __half g_W3h[128 * 128];
__device__ int    g_rowptr[N_NODES + 1];
__device__ int    g_deg[N_NODES];
__device__ int    g_rank[N_EDGES];                 // edge rank within its dst row
__device__ int    g_partial[SCAN_NBLK];            // per-chunk degree sums
__device__ uint2  g_csr[N_EDGES];                  // {src col, val bits}

template <typename T> struct is_half_t { static const bool value = false; };
template <> struct is_half_t<__half>  { static const bool value = true;  };

// ---------------------------------------------------------------------------
// all three weight matrices fp32 -> fp16 in one launch
// ---------------------------------------------------------------------------
__global__ void __launch_bounds__(256, 1)
k_wconv(const float* __restrict__ W1, const float* __restrict__ W2,
        const float* __restrict__ W3,
        __half* __restrict__ W1h, __half* __restrict__ W2h, __half* __restrict__ W3h) {
    int i4 = (blockIdx.x * blockDim.x + threadIdx.x) * 4;
    const float* src; __half* dst; int off;
    if (i4 < 32768)       { src = W1; dst = W1h; off = i4; }
    else if (i4 < 49152)  { src = W2; dst = W2h; off = i4 - 32768; }
    else                  { src = W3; dst = W3h; off = i4 - 49152; }
    float4 v = *reinterpret_cast<const float4*>(&src[off]);
    __half2 p0 = __floats2half2_rn(v.x, v.y);
    __half2 p1 = __floats2half2_rn(v.z, v.w);
    uint2 packed;
    packed.x = *reinterpret_cast<uint32_t*>(&p0);
    packed.y = *reinterpret_cast<uint32_t*>(&p1);
    *reinterpret_cast<uint2*>(&dst[off]) = packed;
}

// ---------------------------------------------------------------------------
// CSR build: histogram(+rank) -> 3-phase parallel scan -> atomic-free scatter
// ---------------------------------------------------------------------------
__global__ void __launch_bounds__(256, 1) k_hist(const int* __restrict__ ei) {
    int e = blockIdx.x * blockDim.x + threadIdx.x;
    if (e < N_EDGES) g_rank[e] = atomicAdd(&g_deg[ei[e]], 1);
}

// phase 1: per-chunk degree sums
__global__ void __launch_bounds__(SCAN_CHUNK, 1) k_partial() {
    __shared__ int red[SCAN_CHUNK];
    int idx = blockIdx.x * SCAN_CHUNK + threadIdx.x;
    red[threadIdx.x] = (idx < N_NODES) ? g_deg[idx] : 0;
    __syncthreads();
    #pragma unroll
    for (int s = SCAN_CHUNK / 2; s > 0; s >>= 1) {
        if (threadIdx.x < s) red[threadIdx.x] += red[threadIdx.x + s];
        __syncthreads();
    }
    if (threadIdx.x == 0) g_partial[blockIdx.x] = red[0];
}

// phase 2: exclusive scan of the 196 partials
__global__ void __launch_bounds__(256, 1) k_scanp() {
    __shared__ int s[256];
    int tid = threadIdx.x;
    s[tid] = (tid < SCAN_NBLK) ? g_partial[tid] : 0;
    __syncthreads();
    #pragma unroll
    for (int off = 1; off < 256; off <<= 1) {
        int v = (tid >= off) ? s[tid - off] : 0;
        __syncthreads();
        s[tid] += v;
        __syncthreads();
    }
    if (tid < SCAN_NBLK) g_partial[tid] = (tid == 0) ? 0 : s[tid - 1];
}

// phase 3: block-local exclusive scan + chunk offset -> rowptr
__global__ void __launch_bounds__(SCAN_CHUNK, 1) k_apply() {
    __shared__ int s[SCAN_CHUNK];
    int tid = threadIdx.x;
    int idx = blockIdx.x * SCAN_CHUNK + tid;
    int d = (idx < N_NODES) ? g_deg[idx] : 0;
    s[tid] = d;
    __syncthreads();
    #pragma unroll
    for (int off = 1; off < SCAN_CHUNK; off <<= 1) {
        int v = (tid >= off) ? s[tid - off] : 0;
        __syncthreads();
        s[tid] += v;
        __syncthreads();
    }
    if (idx < N_NODES)
        g_rowptr[idx] = g_partial[blockIdx.x] + s[tid] - d;
    if (idx == N_NODES - 1 || (blockIdx.x == SCAN_NBLK - 1 && tid == SCAN_CHUNK - 1))
        g_rowptr[N_NODES] = N_EDGES;
}

__global__ void __launch_bounds__(256, 1)
k_scatter(const int* __restrict__ ei, const float* __restrict__ ev) {
    int e = blockIdx.x * blockDim.x + threadIdx.x;
    if (e < N_EDGES) {
        int dst = ei[e];
        int src = ei[N_EDGES + e];
        int pos = g_rowptr[dst] + g_rank[e];       // no atomics
        g_csr[pos] = make_uint2((unsigned)src, __float_as_uint(ev[e]));
    }
}

// ---------------------------------------------------------------------------
// HMMA GEMM (single-buffer K=16 tiles):
// C[M,128](fp16) = A[M,K] @ B[K,128](fp16), fp32 accumulate
// TA=float: converts A fp32->fp16 in-register while staging (GEMM1).
// ---------------------------------------------------------------------------
#define A_STRIDE 24    // halves per A smem row (16 + 8 pad)
#define B_STRIDE 136   // halves per B smem row (128 + 8 pad)

template <typename TA>
__global__ void __launch_bounds__(256)
k_gemm_hmma(const TA* __restrict__ A, const __half* __restrict__ B,
            __half* __restrict__ C, int M, int K) {
    __shared__ __half As[128 * A_STRIDE];
    __shared__ __half Bs[16 * B_STRIDE];

    const int tid  = threadIdx.x;
    const int warp = tid >> 5;
    const int lane = tid & 31;
    const int blockRow = blockIdx.x * 128;
    const int warpRow  = warp * 16;

    float c[16][4];
    #pragma unroll
    for (int j = 0; j < 16; j++)
        #pragma unroll
        for (int q = 0; q < 4; q++) c[j][q] = 0.f;

    const int aRow = warpRow + ((lane >> 3) & 1) * 8 + (lane & 7);
    const int aCol = (lane >> 4) * 8;
    const uint32_t aAddr =
        (uint32_t)__cvta_generic_to_shared(&As[aRow * A_STRIDE + aCol]);
    const int bRow  = ((lane >> 3) & 1) * 8 + (lane & 7);
    const int bColX = (lane >> 4) * 8;

    const int lar = tid >> 1,  lac = (tid & 1) * 8;
    const int lbr = tid >> 4,  lbc = (tid & 15) * 8;
    const int gra = blockRow + lar;
    const bool aValid = (gra < M);

    for (int k0 = 0; k0 < K; k0 += 16) {
        if constexpr (is_half_t<TA>::value) {
            uint4 va = make_uint4(0, 0, 0, 0);
            if (aValid)
                va = *reinterpret_cast<const uint4*>(
                    (const __half*)&A[(size_t)gra * K + k0 + lac]);
            *reinterpret_cast<uint4*>(&As[lar * A_STRIDE + lac]) = va;
        } else {
            __half2 h0 = __float2half2_rn(0.f), h1 = h0, h2 = h0, h3 = h0;
            if (aValid) {
                float4 v0 = *reinterpret_cast<const float4*>(&A[(size_t)gra * K + k0 + lac]);
                float4 v1 = *reinterpret_cast<const float4*>(&A[(size_t)gra * K + k0 + lac + 4]);
                h0 = __floats2half2_rn(v0.x, v0.y);
                h1 = __floats2half2_rn(v0.z, v0.w);
                h2 = __floats2half2_rn(v1.x, v1.y);
                h3 = __floats2half2_rn(v1.z, v1.w);
            }
            uint4 packed;
            packed.x = *reinterpret_cast<uint32_t*>(&h0);
            packed.y = *reinterpret_cast<uint32_t*>(&h1);
            packed.z = *reinterpret_cast<uint32_t*>(&h2);
            packed.w = *reinterpret_cast<uint32_t*>(&h3);
            *reinterpret_cast<uint4*>(&As[lar * A_STRIDE + lac]) = packed;
        }
        *reinterpret_cast<uint4*>(&Bs[lbr * B_STRIDE + lbc]) =
            *reinterpret_cast<const uint4*>(&B[(size_t)(k0 + lbr) * 128 + lbc]);
        __syncthreads();

        uint32_t a0, a1, a2, a3;
        asm volatile("ldmatrix.sync.aligned.m8n8.x4.shared.b16 {%0,%1,%2,%3}, [%4];"
                     : "=r"(a0), "=r"(a1), "=r"(a2), "=r"(a3) : "r"(aAddr));

        #pragma unroll
        for (int j = 0; j < 8; j++) {
            uint32_t b0, b1, b2, b3;
            uint32_t bAddr = (uint32_t)__cvta_generic_to_shared(
                &Bs[bRow * B_STRIDE + j * 16 + bColX]);
            asm volatile("ldmatrix.sync.aligned.m8n8.x4.trans.shared.b16 {%0,%1,%2,%3}, [%4];"
                         : "=r"(b0), "=r"(b1), "=r"(b2), "=r"(b3) : "r"(bAddr));
            asm volatile("mma.sync.aligned.m16n8k16.row.col.f32.f16.f16.f32 "
                         "{%0,%1,%2,%3},{%4,%5,%6,%7},{%8,%9},{%0,%1,%2,%3};"
                         : "+f"(c[2*j][0]), "+f"(c[2*j][1]), "+f"(c[2*j][2]), "+f"(c[2*j][3])
                         : "r"(a0), "r"(a1), "r"(a2), "r"(a3), "r"(b0), "r"(b1));
            asm volatile("mma.sync.aligned.m16n8k16.row.col.f32.f16.f16.f32 "
                         "{%0,%1,%2,%3},{%4,%5,%6,%7},{%8,%9},{%0,%1,%2,%3};"
                         : "+f"(c[2*j+1][0]), "+f"(c[2*j+1][1]), "+f"(c[2*j+1][2]), "+f"(c[2*j+1][3])
                         : "r"(a0), "r"(a1), "r"(a2), "r"(a3), "r"(b2), "r"(b3));
        }
        __syncthreads();
    }

    const int row0 = blockRow + warpRow + (lane >> 2);
    const int row1 = row0 + 8;
    #pragma unroll
    for (int j = 0; j < 16; j++) {
        int col = j * 8 + (lane & 3) * 2;
        if (row0 < M) {
            __half2 p = __floats2half2_rn(c[j][0], c[j][1]);
            *reinterpret_cast<uint32_t*>(&C[(size_t)row0 * 128 + col]) =
                *reinterpret_cast<uint32_t*>(&p);
        }
        if (row1 < M) {
            __half2 p = __floats2half2_rn(c[j][2], c[j][3]);
            *reinterpret_cast<uint32_t*>(&C[(size_t)row1 * 128 + col]) =
                *reinterpret_cast<uint32_t*>(&p);
        }
    }
}

// ---------------------------------------------------------------------------
// SPMM (CSR gather, fp16 src, fp32 accum) + bias + ReLU
// 8-deep batched inner loop: all csr loads issued before gathers (MLP 8)
// ---------------------------------------------------------------------------
__global__ void __launch_bounds__(256, 4)
k_spmm(const __half* __restrict__ support,
       const float* __restrict__ bias,
       float* __restrict__ out32,        // may be null
       __half* __restrict__ out16) {     // may be null
    int gw = (blockIdx.x * blockDim.x + threadIdx.x) >> 5;
    int lane = threadIdx.x & 31;
    if (gw >= N_NODES) return;

    int e   = g_rowptr[gw];
    int end = g_rowptr[gw + 1];

    float ax = 0.f, ay = 0.f, az = 0.f, aw = 0.f;
    const int off = lane * 4;

    for (; e + 8 <= end; e += 8) {
        uint2 cv[8];
        #pragma unroll
        for (int u = 0; u < 8; u++) cv[u] = g_csr[e + u];
        uint2 raw[8];
        #pragma unroll
        for (int u = 0; u < 8; u++)
            raw[u] = *reinterpret_cast<const uint2*>(&support[(size_t)cv[u].x * F + off]);
        #pragma unroll
        for (int u = 0; u < 8; u++) {
            float v = __uint_as_float(cv[u].y);
            float2 f0 = __half22float2(*reinterpret_cast<__half2*>(&raw[u].x));
            float2 f1 = __half22float2(*reinterpret_cast<__half2*>(&raw[u].y));
            ax = fmaf(v, f0.x, ax); ay = fmaf(v, f0.y, ay);
            az = fmaf(v, f1.x, az); aw = fmaf(v, f1.y, aw);
        }
    }
    for (; e < end; e++) {
        uint2 cv = g_csr[e];
        float v = __uint_as_float(cv.y);
        uint2 raw = *reinterpret_cast<const uint2*>(&support[(size_t)cv.x * F + off]);
        float2 f0 = __half22float2(*reinterpret_cast<__half2*>(&raw.x));
        float2 f1 = __half22float2(*reinterpret_cast<__half2*>(&raw.y));
        ax = fmaf(v, f0.x, ax); ay = fmaf(v, f0.y, ay);
        az = fmaf(v, f1.x, az); aw = fmaf(v, f1.y, aw);
    }

    float4 b = *reinterpret_cast<const float4*>(&bias[off]);
    ax = fmaxf(ax + b.x, 0.f); ay = fmaxf(ay + b.y, 0.f);
    az = fmaxf(az + b.z, 0.f); aw = fmaxf(aw + b.w, 0.f);

    if (out32)
        *reinterpret_cast<float4*>(&out32[(size_t)gw * F + off]) =
            make_float4(ax, ay, az, aw);

    if (out16) {
        __half2 p0 = __floats2half2_rn(ax, ay);
        __half2 p1 = __floats2half2_rn(az, aw);
        uint2 packed;
        packed.x = *reinterpret_cast<uint32_t*>(&p0);
        packed.y = *reinterpret_cast<uint32_t*>(&p1);
        *reinterpret_cast<uint2*>(&out16[(size_t)gw * F + off]) = packed;
    }
}

// ---------------------------------------------------------------------------
extern "C" void kernel_launch(void* const* d_in, const int* in_sizes, int n_in,
                              void* d_out, int out_size) {
    const float* x  = (const float*)d_in[0];
    const int*   ei = (const int*)  d_in[1];
    const float* ev = (const float*)d_in[2];
    const float* W1 = (const float*)d_in[3];
    const float* b1 = (const float*)d_in[4];
    const float* W2 = (const float*)d_in[5];
    const float* b2 = (const float*)d_in[6];
    const float* W3 = (const float*)d_in[7];
    const float* b3 = (const float*)d_in[8];
    float* out = (float*)d_out;

    __half *support, *hh, *W1h, *W2h, *W3h;
    int* degPtr;
    cudaGetSymbolAddress((void**)&support, g_support);
    cudaGetSymbolAddress((void**)&hh,      g_hh);
    cudaGetSymbolAddress((void**)&W1h,     g_W1h);
    cudaGetSymbolAddress((void**)&W2h,     g_W2h);
    cudaGetSymbolAddress((void**)&W3h,     g_W3h);
    cudaGetSymbolAddress((void**)&degPtr,  g_deg);

    // weight conversion (merged)
    k_wconv<<<64, 256>>>(W1, W2, W3, W1h, W2h, W3h);

    // CSR build (rank-based scatter, parallel 3-phase scan)
    cudaMemsetAsync(degPtr, 0, N_NODES * sizeof(int), 0);
    k_hist<<<(N_EDGES + 255) / 256, 256>>>(ei);
    k_partial<<<SCAN_NBLK, SCAN_CHUNK>>>();
    k_scanp<<<1, 256>>>();
    k_apply<<<SCAN_NBLK, SCAN_CHUNK>>>();
    k_scatter<<<(N_EDGES + 255) / 256, 256>>>(ei, ev);

    const int gemmGrid = (N_NODES + 127) / 128;
    const int spmmGrid = (N_NODES * 32 + 255) / 256;

    // layer 1: reads fp32 x directly (in-register convert)
    k_gemm_hmma<float><<<gemmGrid, 256>>>(x, W1h, support, N_NODES, 256);
    k_spmm<<<spmmGrid, 256>>>(support, b1, nullptr, hh);

    // layer 2: preds[0]
    k_gemm_hmma<__half><<<gemmGrid, 256>>>(hh, W2h, support, N_NODES, 128);
    k_spmm<<<spmmGrid, 256>>>(support, b2, out, hh);

    // timepoints 1..3 (final one: no fp16 copy needed)
    for (int t = 1; t < T_POINTS; t++) {
        float* cur = out + (size_t)t * N_NODES * F;
        k_gemm_hmma<__half><<<gemmGrid, 256>>>(hh, W3h, support, N_NODES, 128);
        k_spmm<<<spmmGrid, 256>>>(support, b3, cur,
                                  (t == T_POINTS - 1) ? nullptr : hh);
    }
}

// round 16
// speedup vs baseline: 1.0549x; 1.0549x over previous
#include <cuda_runtime.h>
#include <cuda_fp16.h>
#include <stdint.h>

#define N_NODES 100000
#define N_EDGES 3200000
#define F 128
#define T_POINTS 4

#define SCAN_CHUNK 512
#define SCAN_NBLK ((N_NODES + SCAN_CHUNK - 1) / SCAN_CHUNK)   // 196

// ---- scratch (device globals; no allocations allowed) ----
__device__ __half g_support[(size_t)N_NODES * F];  // GEMM out / SPMM gather src
__device__ __half g_hh[(size_t)N_NODES * F];       // layer output fp16 -> next GEMM A
__device__ __half g_W1h[256 * 128];
__device__ __half g_W2h[128 * 128];
__device__ __half g_W3h[128 * 128];
__device__ int    g_rowptr[N_NODES + 1];
__device__ int    g_deg[N_NODES];
__device__ int    g_rank[N_EDGES];                 // edge rank within its dst row
__device__ int    g_partial[SCAN_NBLK];            // per-chunk degree sums
__device__ uint2  g_csr[N_EDGES];                  // {src col, val bits}

template <typename T> struct is_half_t { static const bool value = false; };
template <> struct is_half_t<__half>  { static const bool value = true;  };

// ---------------------------------------------------------------------------
// all three weight matrices fp32 -> fp16 in one launch
// ---------------------------------------------------------------------------
__global__ void __launch_bounds__(256, 1)
k_wconv(const float* __restrict__ W1, const float* __restrict__ W2,
        const float* __restrict__ W3,
        __half* __restrict__ W1h, __half* __restrict__ W2h, __half* __restrict__ W3h) {
    int i4 = (blockIdx.x * blockDim.x + threadIdx.x) * 4;
    const float* src; __half* dst; int off;
    if (i4 < 32768)       { src = W1; dst = W1h; off = i4; }
    else if (i4 < 49152)  { src = W2; dst = W2h; off = i4 - 32768; }
    else                  { src = W3; dst = W3h; off = i4 - 49152; }
    float4 v = *reinterpret_cast<const float4*>(&src[off]);
    __half2 p0 = __floats2half2_rn(v.x, v.y);
    __half2 p1 = __floats2half2_rn(v.z, v.w);
    uint2 packed;
    packed.x = *reinterpret_cast<uint32_t*>(&p0);
    packed.y = *reinterpret_cast<uint32_t*>(&p1);
    *reinterpret_cast<uint2*>(&dst[off]) = packed;
}

// ---------------------------------------------------------------------------
// CSR build: histogram(+rank) -> 3-phase parallel scan -> atomic-free scatter
// ---------------------------------------------------------------------------
__global__ void __launch_bounds__(256, 1) k_hist(const int* __restrict__ ei) {
    int e = blockIdx.x * blockDim.x + threadIdx.x;
    if (e < N_EDGES) g_rank[e] = atomicAdd(&g_deg[ei[e]], 1);
}

// phase 1: per-chunk degree sums
__global__ void __launch_bounds__(SCAN_CHUNK, 1) k_partial() {
    __shared__ int red[SCAN_CHUNK];
    int idx = blockIdx.x * SCAN_CHUNK + threadIdx.x;
    red[threadIdx.x] = (idx < N_NODES) ? g_deg[idx] : 0;
    __syncthreads();
    #pragma unroll
    for (int s = SCAN_CHUNK / 2; s > 0; s >>= 1) {
        if (threadIdx.x < s) red[threadIdx.x] += red[threadIdx.x + s];
        __syncthreads();
    }
    if (threadIdx.x == 0) g_partial[blockIdx.x] = red[0];
}

// phase 2: exclusive scan of the 196 partials
__global__ void __launch_bounds__(256, 1) k_scanp() {
    __shared__ int s[256];
    int tid = threadIdx.x;
    s[tid] = (tid < SCAN_NBLK) ? g_partial[tid] : 0;
    __syncthreads();
    #pragma unroll
    for (int off = 1; off < 256; off <<= 1) {
        int v = (tid >= off) ? s[tid - off] : 0;
        __syncthreads();
        s[tid] += v;
        __syncthreads();
    }
    if (tid < SCAN_NBLK) g_partial[tid] = (tid == 0) ? 0 : s[tid - 1];
}

// phase 3: block-local exclusive scan + chunk offset -> rowptr
__global__ void __launch_bounds__(SCAN_CHUNK, 1) k_apply() {
    __shared__ int s[SCAN_CHUNK];
    int tid = threadIdx.x;
    int idx = blockIdx.x * SCAN_CHUNK + tid;
    int d = (idx < N_NODES) ? g_deg[idx] : 0;
    s[tid] = d;
    __syncthreads();
    #pragma unroll
    for (int off = 1; off < SCAN_CHUNK; off <<= 1) {
        int v = (tid >= off) ? s[tid - off] : 0;
        __syncthreads();
        s[tid] += v;
        __syncthreads();
    }
    if (idx < N_NODES)
        g_rowptr[idx] = g_partial[blockIdx.x] + s[tid] - d;
    if (idx == N_NODES - 1 || (blockIdx.x == SCAN_NBLK - 1 && tid == SCAN_CHUNK - 1))
        g_rowptr[N_NODES] = N_EDGES;
}

__global__ void __launch_bounds__(256, 1)
k_scatter(const int* __restrict__ ei, const float* __restrict__ ev) {
    int e = blockIdx.x * blockDim.x + threadIdx.x;
    if (e < N_EDGES) {
        int dst = ei[e];
        int src = ei[N_EDGES + e];
        int pos = g_rowptr[dst] + g_rank[e];       // no atomics
        g_csr[pos] = make_uint2((unsigned)src, __float_as_uint(ev[e]));
    }
}

// ---------------------------------------------------------------------------
// HMMA GEMM (single-buffer K=16 tiles):
// C[M,128](fp16) = A[M,K] @ B[K,128](fp16), fp32 accumulate
// TA=float: converts A fp32->fp16 in-register while staging (GEMM1).
// ---------------------------------------------------------------------------
#define A_STRIDE 24    // halves per A smem row (16 + 8 pad)
#define B_STRIDE 136   // halves per B smem row (128 + 8 pad)

template <typename TA>
__global__ void __launch_bounds__(256)
k_gemm_hmma(const TA* __restrict__ A, const __half* __restrict__ B,
            __half* __restrict__ C, int M, int K) {
    __shared__ __half As[128 * A_STRIDE];
    __shared__ __half Bs[16 * B_STRIDE];

    const int tid  = threadIdx.x;
    const int warp = tid >> 5;
    const int lane = tid & 31;
    const int blockRow = blockIdx.x * 128;
    const int warpRow  = warp * 16;

    float c[16][4];
    #pragma unroll
    for (int j = 0; j < 16; j++)
        #pragma unroll
        for (int q = 0; q < 4; q++) c[j][q] = 0.f;

    const int aRow = warpRow + ((lane >> 3) & 1) * 8 + (lane & 7);
    const int aCol = (lane >> 4) * 8;
    const uint32_t aAddr =
        (uint32_t)__cvta_generic_to_shared(&As[aRow * A_STRIDE + aCol]);
    const int bRow  = ((lane >> 3) & 1) * 8 + (lane & 7);
    const int bColX = (lane >> 4) * 8;

    const int lar = tid >> 1,  lac = (tid & 1) * 8;
    const int lbr = tid >> 4,  lbc = (tid & 15) * 8;
    const int gra = blockRow + lar;
    const bool aValid = (gra < M);

    for (int k0 = 0; k0 < K; k0 += 16) {
        if constexpr (is_half_t<TA>::value) {
            uint4 va = make_uint4(0, 0, 0, 0);
            if (aValid)
                va = *reinterpret_cast<const uint4*>(
                    (const __half*)&A[(size_t)gra * K + k0 + lac]);
            *reinterpret_cast<uint4*>(&As[lar * A_STRIDE + lac]) = va;
        } else {
            __half2 h0 = __float2half2_rn(0.f), h1 = h0, h2 = h0, h3 = h0;
            if (aValid) {
                float4 v0 = *reinterpret_cast<const float4*>(&A[(size_t)gra * K + k0 + lac]);
                float4 v1 = *reinterpret_cast<const float4*>(&A[(size_t)gra * K + k0 + lac + 4]);
                h0 = __floats2half2_rn(v0.x, v0.y);
                h1 = __floats2half2_rn(v0.z, v0.w);
                h2 = __floats2half2_rn(v1.x, v1.y);
                h3 = __floats2half2_rn(v1.z, v1.w);
            }
            uint4 packed;
            packed.x = *reinterpret_cast<uint32_t*>(&h0);
            packed.y = *reinterpret_cast<uint32_t*>(&h1);
            packed.z = *reinterpret_cast<uint32_t*>(&h2);
            packed.w = *reinterpret_cast<uint32_t*>(&h3);
            *reinterpret_cast<uint4*>(&As[lar * A_STRIDE + lac]) = packed;
        }
        *reinterpret_cast<uint4*>(&Bs[lbr * B_STRIDE + lbc]) =
            *reinterpret_cast<const uint4*>(&B[(size_t)(k0 + lbr) * 128 + lbc]);
        __syncthreads();

        uint32_t a0, a1, a2, a3;
        asm volatile("ldmatrix.sync.aligned.m8n8.x4.shared.b16 {%0,%1,%2,%3}, [%4];"
                     : "=r"(a0), "=r"(a1), "=r"(a2), "=r"(a3) : "r"(aAddr));

        #pragma unroll
        for (int j = 0; j < 8; j++) {
            uint32_t b0, b1, b2, b3;
            uint32_t bAddr = (uint32_t)__cvta_generic_to_shared(
                &Bs[bRow * B_STRIDE + j * 16 + bColX]);
            asm volatile("ldmatrix.sync.aligned.m8n8.x4.trans.shared.b16 {%0,%1,%2,%3}, [%4];"
                         : "=r"(b0), "=r"(b1), "=r"(b2), "=r"(b3) : "r"(bAddr));
            asm volatile("mma.sync.aligned.m16n8k16.row.col.f32.f16.f16.f32 "
                         "{%0,%1,%2,%3},{%4,%5,%6,%7},{%8,%9},{%0,%1,%2,%3};"
                         : "+f"(c[2*j][0]), "+f"(c[2*j][1]), "+f"(c[2*j][2]), "+f"(c[2*j][3])
                         : "r"(a0), "r"(a1), "r"(a2), "r"(a3), "r"(b0), "r"(b1));
            asm volatile("mma.sync.aligned.m16n8k16.row.col.f32.f16.f16.f32 "
                         "{%0,%1,%2,%3},{%4,%5,%6,%7},{%8,%9},{%0,%1,%2,%3};"
                         : "+f"(c[2*j+1][0]), "+f"(c[2*j+1][1]), "+f"(c[2*j+1][2]), "+f"(c[2*j+1][3])
                         : "r"(a0), "r"(a1), "r"(a2), "r"(a3), "r"(b2), "r"(b3));
        }
        __syncthreads();
    }

    const int row0 = blockRow + warpRow + (lane >> 2);
    const int row1 = row0 + 8;
    #pragma unroll
    for (int j = 0; j < 16; j++) {
        int col = j * 8 + (lane & 3) * 2;
        if (row0 < M) {
            __half2 p = __floats2half2_rn(c[j][0], c[j][1]);
            *reinterpret_cast<uint32_t*>(&C[(size_t)row0 * 128 + col]) =
                *reinterpret_cast<uint32_t*>(&p);
        }
        if (row1 < M) {
            __half2 p = __floats2half2_rn(c[j][2], c[j][3]);
            *reinterpret_cast<uint32_t*>(&C[(size_t)row1 * 128 + col]) =
                *reinterpret_cast<uint32_t*>(&p);
        }
    }
}

// ---------------------------------------------------------------------------
// SPMM (CSR gather, fp16 src, fp32 accum) + bias + ReLU
// 4-deep loop, high-occupancy launch bounds (>=6 blocks/SM)
// ---------------------------------------------------------------------------
__global__ void __launch_bounds__(256, 6)
k_spmm(const __half* __restrict__ support,
       const float* __restrict__ bias,
       float* __restrict__ out32,        // may be null
       __half* __restrict__ out16) {     // may be null
    int gw = (blockIdx.x * blockDim.x + threadIdx.x) >> 5;
    int lane = threadIdx.x & 31;
    if (gw >= N_NODES) return;

    int e   = g_rowptr[gw];
    int end = g_rowptr[gw + 1];

    float ax = 0.f, ay = 0.f, az = 0.f, aw = 0.f;
    const int off = lane * 4;

    for (; e + 4 <= end; e += 4) {
        #pragma unroll
        for (int u = 0; u < 4; u++) {
            uint2 cv = g_csr[e + u];
            float v = __uint_as_float(cv.y);
            uint2 raw = *reinterpret_cast<const uint2*>(&support[(size_t)cv.x * F + off]);
            float2 f0 = __half22float2(*reinterpret_cast<__half2*>(&raw.x));
            float2 f1 = __half22float2(*reinterpret_cast<__half2*>(&raw.y));
            ax = fmaf(v, f0.x, ax); ay = fmaf(v, f0.y, ay);
            az = fmaf(v, f1.x, az); aw = fmaf(v, f1.y, aw);
        }
    }
    for (; e < end; e++) {
        uint2 cv = g_csr[e];
        float v = __uint_as_float(cv.y);
        uint2 raw = *reinterpret_cast<const uint2*>(&support[(size_t)cv.x * F + off]);
        float2 f0 = __half22float2(*reinterpret_cast<__half2*>(&raw.x));
        float2 f1 = __half22float2(*reinterpret_cast<__half2*>(&raw.y));
        ax = fmaf(v, f0.x, ax); ay = fmaf(v, f0.y, ay);
        az = fmaf(v, f1.x, az); aw = fmaf(v, f1.y, aw);
    }

    float4 b = *reinterpret_cast<const float4*>(&bias[off]);
    ax = fmaxf(ax + b.x, 0.f); ay = fmaxf(ay + b.y, 0.f);
    az = fmaxf(az + b.z, 0.f); aw = fmaxf(aw + b.w, 0.f);

    if (out32)
        *reinterpret_cast<float4*>(&out32[(size_t)gw * F + off]) =
            make_float4(ax, ay, az, aw);

    if (out16) {
        __half2 p0 = __floats2half2_rn(ax, ay);
        __half2 p1 = __floats2half2_rn(az, aw);
        uint2 packed;
        packed.x = *reinterpret_cast<uint32_t*>(&p0);
        packed.y = *reinterpret_cast<uint32_t*>(&p1);
        *reinterpret_cast<uint2*>(&out16[(size_t)gw * F + off]) = packed;
    }
}

// ---------------------------------------------------------------------------
extern "C" void kernel_launch(void* const* d_in, const int* in_sizes, int n_in,
                              void* d_out, int out_size) {
    const float* x  = (const float*)d_in[0];
    const int*   ei = (const int*)  d_in[1];
    const float* ev = (const float*)d_in[2];
    const float* W1 = (const float*)d_in[3];
    const float* b1 = (const float*)d_in[4];
    const float* W2 = (const float*)d_in[5];
    const float* b2 = (const float*)d_in[6];
    const float* W3 = (const float*)d_in[7];
    const float* b3 = (const float*)d_in[8];
    float* out = (float*)d_out;

    __half *support, *hh, *W1h, *W2h, *W3h;
    int* degPtr;
    cudaGetSymbolAddress((void**)&support, g_support);
    cudaGetSymbolAddress((void**)&hh,      g_hh);
    cudaGetSymbolAddress((void**)&W1h,     g_W1h);
    cudaGetSymbolAddress((void**)&W2h,     g_W2h);
    cudaGetSymbolAddress((void**)&W3h,     g_W3h);
    cudaGetSymbolAddress((void**)&degPtr,  g_deg);

    // weight conversion (merged)
    k_wconv<<<64, 256>>>(W1, W2, W3, W1h, W2h, W3h);

    // CSR build (rank-based scatter, parallel 3-phase scan)
    cudaMemsetAsync(degPtr, 0, N_NODES * sizeof(int), 0);
    k_hist<<<(N_EDGES + 255) / 256, 256>>>(ei);
    k_partial<<<SCAN_NBLK, SCAN_CHUNK>>>();
    k_scanp<<<1, 256>>>();
    k_apply<<<SCAN_NBLK, SCAN_CHUNK>>>();
    k_scatter<<<(N_EDGES + 255) / 256, 256>>>(ei, ev);

    const int gemmGrid = (N_NODES + 127) / 128;
    const int spmmGrid = (N_NODES * 32 + 255) / 256;

    // layer 1: reads fp32 x directly (in-register convert)
    k_gemm_hmma<float><<<gemmGrid, 256>>>(x, W1h, support, N_NODES, 256);
    k_spmm<<<spmmGrid, 256>>>(support, b1, nullptr, hh);

    // layer 2: preds[0]
    k_gemm_hmma<__half><<<gemmGrid, 256>>>(hh, W2h, support, N_NODES, 128);
    k_spmm<<<spmmGrid, 256>>>(support, b2, out, hh);

    // timepoints 1..3 (final one: no fp16 copy needed)
    for (int t = 1; t < T_POINTS; t++) {
        float* cur = out + (size_t)t * N_NODES * F;
        k_gemm_hmma<__half><<<gemmGrid, 256>>>(hh, W3h, support, N_NODES, 128);
        k_spmm<<<spmmGrid, 256>>>(support, b3, cur,
                                  (t == T_POINTS - 1) ? nullptr : hh);
    }
}

// round 17
// speedup vs baseline: 1.0756x; 1.0196x over previous
#include <cuda_runtime.h>
#include <cuda_fp16.h>
#include <stdint.h>

#define N_NODES 100000
#define N_EDGES 3200000
#define F 128
#define T_POINTS 4

#define SCAN_CHUNK 512
#define SCAN_NBLK ((N_NODES + SCAN_CHUNK - 1) / SCAN_CHUNK)   // 196

// ---- scratch (device globals; no allocations allowed) ----
__device__ __half g_support[(size_t)N_NODES * F];  // GEMM out / SPMM gather src
__device__ __half g_hh[(size_t)N_NODES * F];       // layer output fp16 -> next GEMM A
__device__ __half g_W1h[256 * 128];
__device__ __half g_W2h[128 * 128];
__device__ __half g_W3h[128 * 128];
__device__ int    g_rowptr[N_NODES + 1];
__device__ int    g_deg[N_NODES];
__device__ int    g_rank[N_EDGES];                 // edge rank within its dst row
__device__ int    g_partial[SCAN_NBLK];            // per-chunk degree sums
__device__ uint2  g_csr[N_EDGES];                  // {src col, val bits}

template <typename T> struct is_half_t { static const bool value = false; };
template <> struct is_half_t<__half>  { static const bool value = true;  };

// ---------------------------------------------------------------------------
// all three weight matrices fp32 -> fp16 in one launch
// ---------------------------------------------------------------------------
__global__ void __launch_bounds__(256, 1)
k_wconv(const float* __restrict__ W1, const float* __restrict__ W2,
        const float* __restrict__ W3,
        __half* __restrict__ W1h, __half* __restrict__ W2h, __half* __restrict__ W3h) {
    int i4 = (blockIdx.x * blockDim.x + threadIdx.x) * 4;
    const float* src; __half* dst; int off;
    if (i4 < 32768)       { src = W1; dst = W1h; off = i4; }
    else if (i4 < 49152)  { src = W2; dst = W2h; off = i4 - 32768; }
    else                  { src = W3; dst = W3h; off = i4 - 49152; }
    float4 v = *reinterpret_cast<const float4*>(&src[off]);
    __half2 p0 = __floats2half2_rn(v.x, v.y);
    __half2 p1 = __floats2half2_rn(v.z, v.w);
    uint2 packed;
    packed.x = *reinterpret_cast<uint32_t*>(&p0);
    packed.y = *reinterpret_cast<uint32_t*>(&p1);
    *reinterpret_cast<uint2*>(&dst[off]) = packed;
}

// ---------------------------------------------------------------------------
// CSR build: histogram(+rank) -> 3-phase parallel scan -> atomic-free scatter
// ---------------------------------------------------------------------------
__global__ void __launch_bounds__(256, 1) k_hist(const int* __restrict__ ei) {
    int e = blockIdx.x * blockDim.x + threadIdx.x;
    if (e < N_EDGES) g_rank[e] = atomicAdd(&g_deg[ei[e]], 1);
}

// phase 1: per-chunk degree sums
__global__ void __launch_bounds__(SCAN_CHUNK, 1) k_partial() {
    __shared__ int red[SCAN_CHUNK];
    int idx = blockIdx.x * SCAN_CHUNK + threadIdx.x;
    red[threadIdx.x] = (idx < N_NODES) ? g_deg[idx] : 0;
    __syncthreads();
    #pragma unroll
    for (int s = SCAN_CHUNK / 2; s > 0; s >>= 1) {
        if (threadIdx.x < s) red[threadIdx.x] += red[threadIdx.x + s];
        __syncthreads();
    }
    if (threadIdx.x == 0) g_partial[blockIdx.x] = red[0];
}

// phase 2: exclusive scan of the 196 partials
__global__ void __launch_bounds__(256, 1) k_scanp() {
    __shared__ int s[256];
    int tid = threadIdx.x;
    s[tid] = (tid < SCAN_NBLK) ? g_partial[tid] : 0;
    __syncthreads();
    #pragma unroll
    for (int off = 1; off < 256; off <<= 1) {
        int v = (tid >= off) ? s[tid - off] : 0;
        __syncthreads();
        s[tid] += v;
        __syncthreads();
    }
    if (tid < SCAN_NBLK) g_partial[tid] = (tid == 0) ? 0 : s[tid - 1];
}

// phase 3: block-local exclusive scan + chunk offset -> rowptr
__global__ void __launch_bounds__(SCAN_CHUNK, 1) k_apply() {
    __shared__ int s[SCAN_CHUNK];
    int tid = threadIdx.x;
    int idx = blockIdx.x * SCAN_CHUNK + tid;
    int d = (idx < N_NODES) ? g_deg[idx] : 0;
    s[tid] = d;
    __syncthreads();
    #pragma unroll
    for (int off = 1; off < SCAN_CHUNK; off <<= 1) {
        int v = (tid >= off) ? s[tid - off] : 0;
        __syncthreads();
        s[tid] += v;
        __syncthreads();
    }
    if (idx < N_NODES)
        g_rowptr[idx] = g_partial[blockIdx.x] + s[tid] - d;
    if (idx == N_NODES - 1 || (blockIdx.x == SCAN_NBLK - 1 && tid == SCAN_CHUNK - 1))
        g_rowptr[N_NODES] = N_EDGES;
}

__global__ void __launch_bounds__(256, 1)
k_scatter(const int* __restrict__ ei, const float* __restrict__ ev) {
    int e = blockIdx.x * blockDim.x + threadIdx.x;
    if (e < N_EDGES) {
        int dst = ei[e];
        int src = ei[N_EDGES + e];
        int pos = g_rowptr[dst] + g_rank[e];       // no atomics
        g_csr[pos] = make_uint2((unsigned)src, __float_as_uint(ev[e]));
    }
}

// ---------------------------------------------------------------------------
// HMMA GEMM (single-buffer K=16 tiles):
// C[M,128](fp16) = A[M,K] @ B[K,128](fp16), fp32 accumulate
// TA=float: converts A fp32->fp16 in-register while staging (GEMM1).
// ---------------------------------------------------------------------------
#define A_STRIDE 24    // halves per A smem row (16 + 8 pad)
#define B_STRIDE 136   // halves per B smem row (128 + 8 pad)

template <typename TA>
__global__ void __launch_bounds__(256)
k_gemm_hmma(const TA* __restrict__ A, const __half* __restrict__ B,
            __half* __restrict__ C, int M, int K) {
    __shared__ __half As[128 * A_STRIDE];
    __shared__ __half Bs[16 * B_STRIDE];

    const int tid  = threadIdx.x;
    const int warp = tid >> 5;
    const int lane = tid & 31;
    const int blockRow = blockIdx.x * 128;
    const int warpRow  = warp * 16;

    float c[16][4];
    #pragma unroll
    for (int j = 0; j < 16; j++)
        #pragma unroll
        for (int q = 0; q < 4; q++) c[j][q] = 0.f;

    const int aRow = warpRow + ((lane >> 3) & 1) * 8 + (lane & 7);
    const int aCol = (lane >> 4) * 8;
    const uint32_t aAddr =
        (uint32_t)__cvta_generic_to_shared(&As[aRow * A_STRIDE + aCol]);
    const int bRow  = ((lane >> 3) & 1) * 8 + (lane & 7);
    const int bColX = (lane >> 4) * 8;

    const int lar = tid >> 1,  lac = (tid & 1) * 8;
    const int lbr = tid >> 4,  lbc = (tid & 15) * 8;
    const int gra = blockRow + lar;
    const bool aValid = (gra < M);

    for (int k0 = 0; k0 < K; k0 += 16) {
        if constexpr (is_half_t<TA>::value) {
            uint4 va = make_uint4(0, 0, 0, 0);
            if (aValid)
                va = *reinterpret_cast<const uint4*>(
                    (const __half*)&A[(size_t)gra * K + k0 + lac]);
            *reinterpret_cast<uint4*>(&As[lar * A_STRIDE + lac]) = va;
        } else {
            __half2 h0 = __float2half2_rn(0.f), h1 = h0, h2 = h0, h3 = h0;
            if (aValid) {
                float4 v0 = *reinterpret_cast<const float4*>(&A[(size_t)gra * K + k0 + lac]);
                float4 v1 = *reinterpret_cast<const float4*>(&A[(size_t)gra * K + k0 + lac + 4]);
                h0 = __floats2half2_rn(v0.x, v0.y);
                h1 = __floats2half2_rn(v0.z, v0.w);
                h2 = __floats2half2_rn(v1.x, v1.y);
                h3 = __floats2half2_rn(v1.z, v1.w);
            }
            uint4 packed;
            packed.x = *reinterpret_cast<uint32_t*>(&h0);
            packed.y = *reinterpret_cast<uint32_t*>(&h1);
            packed.z = *reinterpret_cast<uint32_t*>(&h2);
            packed.w = *reinterpret_cast<uint32_t*>(&h3);
            *reinterpret_cast<uint4*>(&As[lar * A_STRIDE + lac]) = packed;
        }
        *reinterpret_cast<uint4*>(&Bs[lbr * B_STRIDE + lbc]) =
            *reinterpret_cast<const uint4*>(&B[(size_t)(k0 + lbr) * 128 + lbc]);
        __syncthreads();

        uint32_t a0, a1, a2, a3;
        asm volatile("ldmatrix.sync.aligned.m8n8.x4.shared.b16 {%0,%1,%2,%3}, [%4];"
                     : "=r"(a0), "=r"(a1), "=r"(a2), "=r"(a3) : "r"(aAddr));

        #pragma unroll
        for (int j = 0; j < 8; j++) {
            uint32_t b0, b1, b2, b3;
            uint32_t bAddr = (uint32_t)__cvta_generic_to_shared(
                &Bs[bRow * B_STRIDE + j * 16 + bColX]);
            asm volatile("ldmatrix.sync.aligned.m8n8.x4.trans.shared.b16 {%0,%1,%2,%3}, [%4];"
                         : "=r"(b0), "=r"(b1), "=r"(b2), "=r"(b3) : "r"(bAddr));
            asm volatile("mma.sync.aligned.m16n8k16.row.col.f32.f16.f16.f32 "
                         "{%0,%1,%2,%3},{%4,%5,%6,%7},{%8,%9},{%0,%1,%2,%3};"
                         : "+f"(c[2*j][0]), "+f"(c[2*j][1]), "+f"(c[2*j][2]), "+f"(c[2*j][3])
                         : "r"(a0), "r"(a1), "r"(a2), "r"(a3), "r"(b0), "r"(b1));
            asm volatile("mma.sync.aligned.m16n8k16.row.col.f32.f16.f16.f32 "
                         "{%0,%1,%2,%3},{%4,%5,%6,%7},{%8,%9},{%0,%1,%2,%3};"
                         : "+f"(c[2*j+1][0]), "+f"(c[2*j+1][1]), "+f"(c[2*j+1][2]), "+f"(c[2*j+1][3])
                         : "r"(a0), "r"(a1), "r"(a2), "r"(a3), "r"(b2), "r"(b3));
        }
        __syncthreads();
    }

    const int row0 = blockRow + warpRow + (lane >> 2);
    const int row1 = row0 + 8;
    #pragma unroll
    for (int j = 0; j < 16; j++) {
        int col = j * 8 + (lane & 3) * 2;
        if (row0 < M) {
            __half2 p = __floats2half2_rn(c[j][0], c[j][1]);
            *reinterpret_cast<uint32_t*>(&C[(size_t)row0 * 128 + col]) =
                *reinterpret_cast<uint32_t*>(&p);
        }
        if (row1 < M) {
            __half2 p = __floats2half2_rn(c[j][2], c[j][3]);
            *reinterpret_cast<uint32_t*>(&C[(size_t)row1 * 128 + col]) =
                *reinterpret_cast<uint32_t*>(&p);
        }
    }
}

// ---------------------------------------------------------------------------
// SPMM (CSR gather, fp16 src, fp32 accum) + bias + ReLU
// 4-deep loop, max-occupancy launch bounds (8 blocks/SM, 64 warps)
// ---------------------------------------------------------------------------
__global__ void __launch_bounds__(256, 8)
k_spmm(const __half* __restrict__ support,
       const float* __restrict__ bias,
       float* __restrict__ out32,        // may be null
       __half* __restrict__ out16) {     // may be null
    int gw = (blockIdx.x * blockDim.x + threadIdx.x) >> 5;
    int lane = threadIdx.x & 31;
    if (gw >= N_NODES) return;

    int e   = g_rowptr[gw];
    int end = g_rowptr[gw + 1];

    float ax = 0.f, ay = 0.f, az = 0.f, aw = 0.f;
    const int off = lane * 4;

    for (; e + 4 <= end; e += 4) {
        #pragma unroll
        for (int u = 0; u < 4; u++) {
            uint2 cv = g_csr[e + u];
            float v = __uint_as_float(cv.y);
            uint2 raw = *reinterpret_cast<const uint2*>(&support[(size_t)cv.x * F + off]);
            float2 f0 = __half22float2(*reinterpret_cast<__half2*>(&raw.x));
            float2 f1 = __half22float2(*reinterpret_cast<__half2*>(&raw.y));
            ax = fmaf(v, f0.x, ax); ay = fmaf(v, f0.y, ay);
            az = fmaf(v, f1.x, az); aw = fmaf(v, f1.y, aw);
        }
    }
    for (; e < end; e++) {
        uint2 cv = g_csr[e];
        float v = __uint_as_float(cv.y);
        uint2 raw = *reinterpret_cast<const uint2*>(&support[(size_t)cv.x * F + off]);
        float2 f0 = __half22float2(*reinterpret_cast<__half2*>(&raw.x));
        float2 f1 = __half22float2(*reinterpret_cast<__half2*>(&raw.y));
        ax = fmaf(v, f0.x, ax); ay = fmaf(v, f0.y, ay);
        az = fmaf(v, f1.x, az); aw = fmaf(v, f1.y, aw);
    }

    float4 b = *reinterpret_cast<const float4*>(&bias[off]);
    ax = fmaxf(ax + b.x, 0.f); ay = fmaxf(ay + b.y, 0.f);
    az = fmaxf(az + b.z, 0.f); aw = fmaxf(aw + b.w, 0.f);

    if (out32)
        *reinterpret_cast<float4*>(&out32[(size_t)gw * F + off]) =
            make_float4(ax, ay, az, aw);

    if (out16) {
        __half2 p0 = __floats2half2_rn(ax, ay);
        __half2 p1 = __floats2half2_rn(az, aw);
        uint2 packed;
        packed.x = *reinterpret_cast<uint32_t*>(&p0);
        packed.y = *reinterpret_cast<uint32_t*>(&p1);
        *reinterpret_cast<uint2*>(&out16[(size_t)gw * F + off]) = packed;
    }
}

// ---------------------------------------------------------------------------
extern "C" void kernel_launch(void* const* d_in, const int* in_sizes, int n_in,
                              void* d_out, int out_size) {
    const float* x  = (const float*)d_in[0];
    const int*   ei = (const int*)  d_in[1];
    const float* ev = (const float*)d_in[2];
    const float* W1 = (const float*)d_in[3];
    const float* b1 = (const float*)d_in[4];
    const float* W2 = (const float*)d_in[5];
    const float* b2 = (const float*)d_in[6];
    const float* W3 = (const float*)d_in[7];
    const float* b3 = (const float*)d_in[8];
    float* out = (float*)d_out;

    __half *support, *hh, *W1h, *W2h, *W3h;
    int* degPtr;
    cudaGetSymbolAddress((void**)&support, g_support);
    cudaGetSymbolAddress((void**)&hh,      g_hh);
    cudaGetSymbolAddress((void**)&W1h,     g_W1h);
    cudaGetSymbolAddress((void**)&W2h,     g_W2h);
    cudaGetSymbolAddress((void**)&W3h,     g_W3h);
    cudaGetSymbolAddress((void**)&degPtr,  g_deg);

    // weight conversion (merged)
    k_wconv<<<64, 256>>>(W1, W2, W3, W1h, W2h, W3h);

    // CSR build (rank-based scatter, parallel 3-phase scan)
    cudaMemsetAsync(degPtr, 0, N_NODES * sizeof(int), 0);
    k_hist<<<(N_EDGES + 255) / 256, 256>>>(ei);
    k_partial<<<SCAN_NBLK, SCAN_CHUNK>>>();
    k_scanp<<<1, 256>>>();
    k_apply<<<SCAN_NBLK, SCAN_CHUNK>>>();
    k_scatter<<<(N_EDGES + 255) / 256, 256>>>(ei, ev);

    const int gemmGrid = (N_NODES + 127) / 128;
    const int spmmGrid = (N_NODES * 32 + 255) / 256;

    // layer 1: reads fp32 x directly (in-register convert)
    k_gemm_hmma<float><<<gemmGrid, 256>>>(x, W1h, support, N_NODES, 256);
    k_spmm<<<spmmGrid, 256>>>(support, b1, nullptr, hh);

    // layer 2: preds[0]
    k_gemm_hmma<__half><<<gemmGrid, 256>>>(hh, W2h, support, N_NODES, 128);
    k_spmm<<<spmmGrid, 256>>>(support, b2, out, hh);

    // timepoints 1..3 (final one: no fp16 copy needed)
    for (int t = 1; t < T_POINTS; t++) {
        float* cur = out + (size_t)t * N_NODES * F;
        k_gemm_hmma<__half><<<gemmGrid, 256>>>(hh, W3h, support, N_NODES, 128);
        k_spmm<<<spmmGrid, 256>>>(support, b3, cur,
                                  (t == T_POINTS - 1) ? nullptr : hh);
    }
}